// round 1
// baseline (speedup 1.0000x reference)
#include <cuda_runtime.h>
#include <cuda_bf16.h>

#define N_POINTS 2097152
#define NHEADS   16
#define FEAT     2
#define D_IN     32
#define HID      64
#define NOUT     3
#define M_TBL    524288

#define THREADS  128
#define BLOCKS   4096   // 524288 threads, 4 points each

__global__ __launch_bounds__(THREADS)
void ngp_mlp_kernel(const int* __restrict__ idx,
                    const float* __restrict__ tables,   // [H, M, F]
                    const float* __restrict__ gW1, const float* __restrict__ gb1,
                    const float* __restrict__ gW2, const float* __restrict__ gb2,
                    const float* __restrict__ gW3, const float* __restrict__ gb3,
                    const float* __restrict__ gW4, const float* __restrict__ gb4,
                    float* __restrict__ out)
{
    __shared__ float sW1[D_IN * HID];   // 2048
    __shared__ float sW2[HID * HID];    // 4096
    __shared__ float sW3[HID * HID];    // 4096
    __shared__ float sW4[HID * NOUT];   // 192
    __shared__ float sb1[HID], sb2[HID], sb3[HID], sb4[NOUT];

    const int t = threadIdx.x;

    // Stage weights in shared (broadcast-read later)
    for (int i = t; i < D_IN * HID; i += THREADS) sW1[i] = gW1[i];
    for (int i = t; i < HID * HID;  i += THREADS) sW2[i] = gW2[i];
    for (int i = t; i < HID * HID;  i += THREADS) sW3[i] = gW3[i];
    for (int i = t; i < HID * NOUT; i += THREADS) sW4[i] = gW4[i];
    if (t < HID) { sb1[t] = gb1[t]; sb2[t] = gb2[t]; sb3[t] = gb3[t]; }
    if (t < NOUT) sb4[t] = gb4[t];
    __syncthreads();

    for (long n = (long)blockIdx.x * THREADS + t; n < N_POINTS;
         n += (long)gridDim.x * THREADS)
    {
        // ---- gather: x[32] = concat_h tables[h][idx[n,h]] ----
        float x[D_IN];
        #pragma unroll
        for (int h = 0; h < NHEADS; h += 4) {
            int4 iv = *reinterpret_cast<const int4*>(idx + n * NHEADS + h);
            float2 v0 = *reinterpret_cast<const float2*>(
                tables + ((long)(h + 0) * M_TBL + iv.x) * FEAT);
            float2 v1 = *reinterpret_cast<const float2*>(
                tables + ((long)(h + 1) * M_TBL + iv.y) * FEAT);
            float2 v2 = *reinterpret_cast<const float2*>(
                tables + ((long)(h + 2) * M_TBL + iv.z) * FEAT);
            float2 v3 = *reinterpret_cast<const float2*>(
                tables + ((long)(h + 3) * M_TBL + iv.w) * FEAT);
            x[(h + 0) * FEAT + 0] = v0.x; x[(h + 0) * FEAT + 1] = v0.y;
            x[(h + 1) * FEAT + 0] = v1.x; x[(h + 1) * FEAT + 1] = v1.y;
            x[(h + 2) * FEAT + 0] = v2.x; x[(h + 2) * FEAT + 1] = v2.y;
            x[(h + 3) * FEAT + 0] = v3.x; x[(h + 3) * FEAT + 1] = v3.y;
        }

        // ---- layer 1: 32 -> 64, relu ----
        float h1[HID];
        #pragma unroll
        for (int j = 0; j < HID; j++) h1[j] = sb1[j];
        #pragma unroll 4
        for (int i = 0; i < D_IN; i++) {
            const float xi = x[i];
            #pragma unroll
            for (int j = 0; j < HID; j += 4) {
                float4 w = *reinterpret_cast<const float4*>(&sW1[i * HID + j]);
                h1[j + 0] += xi * w.x; h1[j + 1] += xi * w.y;
                h1[j + 2] += xi * w.z; h1[j + 3] += xi * w.w;
            }
        }
        #pragma unroll
        for (int j = 0; j < HID; j++) h1[j] = fmaxf(h1[j], 0.0f);

        // ---- layer 2: 64 -> 64, relu ----
        float h2[HID];
        #pragma unroll
        for (int j = 0; j < HID; j++) h2[j] = sb2[j];
        #pragma unroll 4
        for (int i = 0; i < HID; i++) {
            const float xi = h1[i];
            #pragma unroll
            for (int j = 0; j < HID; j += 4) {
                float4 w = *reinterpret_cast<const float4*>(&sW2[i * HID + j]);
                h2[j + 0] += xi * w.x; h2[j + 1] += xi * w.y;
                h2[j + 2] += xi * w.z; h2[j + 3] += xi * w.w;
            }
        }
        #pragma unroll
        for (int j = 0; j < HID; j++) h2[j] = fmaxf(h2[j], 0.0f);

        // ---- layer 3: 64 -> 64, relu (reuse h1) ----
        #pragma unroll
        for (int j = 0; j < HID; j++) h1[j] = sb3[j];
        #pragma unroll 4
        for (int i = 0; i < HID; i++) {
            const float xi = h2[i];
            #pragma unroll
            for (int j = 0; j < HID; j += 4) {
                float4 w = *reinterpret_cast<const float4*>(&sW3[i * HID + j]);
                h1[j + 0] += xi * w.x; h1[j + 1] += xi * w.y;
                h1[j + 2] += xi * w.z; h1[j + 3] += xi * w.w;
            }
        }
        #pragma unroll
        for (int j = 0; j < HID; j++) h1[j] = fmaxf(h1[j], 0.0f);

        // ---- layer 4: 64 -> 3 ----
        float o0 = sb4[0], o1 = sb4[1], o2 = sb4[2];
        #pragma unroll
        for (int i = 0; i < HID; i++) {
            const float xi = h1[i];
            o0 += xi * sW4[i * NOUT + 0];
            o1 += xi * sW4[i * NOUT + 1];
            o2 += xi * sW4[i * NOUT + 2];
        }
        out[n * NOUT + 0] = o0;
        out[n * NOUT + 1] = o1;
        out[n * NOUT + 2] = o2;
    }
}

extern "C" void kernel_launch(void* const* d_in, const int* in_sizes, int n_in,
                              void* d_out, int out_size)
{
    const int*   idx    = (const int*)  d_in[0];
    const float* tables = (const float*)d_in[1];
    const float* W1 = (const float*)d_in[2];
    const float* b1 = (const float*)d_in[3];
    const float* W2 = (const float*)d_in[4];
    const float* b2 = (const float*)d_in[5];
    const float* W3 = (const float*)d_in[6];
    const float* b3 = (const float*)d_in[7];
    const float* W4 = (const float*)d_in[8];
    const float* b4 = (const float*)d_in[9];
    float* out = (float*)d_out;

    ngp_mlp_kernel<<<BLOCKS, THREADS>>>(idx, tables,
                                        W1, b1, W2, b2, W3, b3, W4, b4, out);
}